// round 16
// baseline (speedup 1.0000x reference)
#include <cuda_runtime.h>
#include <cuda_fp16.h>
#include <mma.h>
#include <math.h>

using namespace nvcuda;

#define MAXN 50000
#define MAXE 800000
#define CIN0 128
#define COUT 64
#define NEG_SLOPE 0.2f

// ---------------- device scratch (double-buffered) ----------------
// hp stored fp16, PERMUTED: position p = half2(channel p, channel p+32); row = 128B
__device__ __half2 g_hpA[MAXN * 32];
__device__ __half2 g_hpB[MAXN * 32];
__device__ float   g_asA[MAXN], g_adA[MAXN];
__device__ float   g_asB[MAXN], g_adB[MAXN];
__device__ int     g_rowptr[MAXN + 1];
__device__ int     g_deg[MAXN];
__device__ int     g_cnt[MAXN];
__device__ int     g_esrc[MAXE];
__device__ int     g_tsum[64];

// ---------------- packed f32x2 helpers ----------------
__device__ __forceinline__ float2 ffma2(float2 a, float2 b, float2 c) {
    unsigned long long ra = *(unsigned long long*)&a;
    unsigned long long rb = *(unsigned long long*)&b;
    unsigned long long rc = *(unsigned long long*)&c;
    unsigned long long rd;
    asm("fma.rn.f32x2 %0, %1, %2, %3;" : "=l"(rd) : "l"(ra), "l"(rb), "l"(rc));
    return *(float2*)&rd;
}
__device__ __forceinline__ float2 dup2(float x) { return make_float2(x, x); }
__device__ __forceinline__ float leaky(float e) { return e > 0.f ? e : NEG_SLOPE * e; }

// fp16 hp row accessor: row = 128 bytes; lane16 owns 8B (channels 2l,2l+32,2l+1,2l+33)
__device__ __forceinline__ uint2 hp_row16(const __half2* hp, int i, int lane16) {
    return *((const uint2*)((const char*)hp + ((unsigned)i << 7)) + lane16);
}
__device__ __forceinline__ void unpack_hp(uint2 r, float2& f0, float2& f1) {
    f0 = __half22float2(*(const __half2*)&r.x);
    f1 = __half22float2(*(const __half2*)&r.y);
}

// ---------------- 16-lane gather via smem (w,src) pairs; LDS.128 = 2 edges ----
__device__ __forceinline__ void gather16s(unsigned gmask, float2* pairs,
                                          float w, int src, int cnt, int lane16,
                                          const __half2* __restrict__ hp,
                                          float2& accA, float2& accB) {
    __syncwarp(gmask);
    pairs[lane16] = make_float2(w, __int_as_float(src));
    __syncwarp(gmask);
    int cnt_r = (cnt + 3) & ~3;        // zero-padded: safe to over-read
    for (int t = 0; t < cnt_r; t += 4) {
        float4 p01 = *(const float4*)&pairs[t];
        float4 p23 = *(const float4*)&pairs[t + 2];
        int i0 = __float_as_int(p01.y), i1 = __float_as_int(p01.w);
        int i2 = __float_as_int(p23.y), i3 = __float_as_int(p23.w);
        uint2 r0 = hp_row16(hp, i0, lane16);
        uint2 r1 = hp_row16(hp, i1, lane16);
        uint2 r2 = hp_row16(hp, i2, lane16);
        uint2 r3 = hp_row16(hp, i3, lane16);
        float2 a0, b0, a1, b1, a2, b2, a3, b3;
        unpack_hp(r0, a0, b0);
        unpack_hp(r1, a1, b1);
        unpack_hp(r2, a2, b2);
        unpack_hp(r3, a3, b3);
        accA = ffma2(dup2(p01.x), a0, accA); accB = ffma2(dup2(p01.x), b0, accB);
        accA = ffma2(dup2(p01.z), a1, accA); accB = ffma2(dup2(p01.z), b1, accB);
        accA = ffma2(dup2(p23.x), a2, accA); accB = ffma2(dup2(p23.x), b2, accB);
        accA = ffma2(dup2(p23.z), a3, accA); accB = ffma2(dup2(p23.z), b3, accB);
    }
}

// gather + normalize for one node given pre-fetched front data
__device__ __forceinline__ float4 agg_body(unsigned gmask, float2* pairs,
                                           const __half2* __restrict__ hp,
                                           const float* __restrict__ as,
                                           int start, int end, float ad_n, float w_self,
                                           uint2 vsr, int s0, int s1, float a0, float a1,
                                           int lane16) {
    int j0 = start + lane16, j1 = j0 + 16;
    float w0 = (j0 < end) ? __expf(leaky(a0 + ad_n)) : 0.f;
    float w1 = (j1 < end) ? __expf(leaky(a1 + ad_n)) : 0.f;
    int   sj0 = (j0 < end) ? s0 : 0;
    int   sj1 = (j1 < end) ? s1 : 0;
    float wsum = w0 + w1 + ((lane16 == 0) ? w_self : 0.f);
    float2 vsA, vsB;
    unpack_hp(vsr, vsA, vsB);
    float2 accA = make_float2(w_self * vsA.x, w_self * vsA.y);
    float2 accB = make_float2(w_self * vsB.x, w_self * vsB.y);
    int deg = end - start;
    if (deg > 0)  gather16s(gmask, pairs, w0, sj0, min(16, deg),      lane16, hp, accA, accB);
    if (deg > 16) gather16s(gmask, pairs, w1, sj1, min(16, deg - 16), lane16, hp, accA, accB);
    for (int jb = start + 32; jb < end; jb += 16) {   // rare: deg > 32 (shfl path)
        int jj = jb + lane16;
        int cnt = min(16, end - jb);
        int sj = 0; float w = 0.f;
        if (jj < end) {
            sj = __ldg(&g_esrc[jj]);
            w = __expf(leaky(__ldg(&as[sj]) + ad_n));
        }
        wsum += w;
        for (int t = 0; t < cnt; t++) {
            float wt = __shfl_sync(gmask, w, t, 16);
            int   it = __shfl_sync(gmask, sj, t, 16);
            uint2 rt = hp_row16(hp, it, lane16);
            float2 at, bt;
            unpack_hp(rt, at, bt);
            accA = ffma2(dup2(wt), at, accA);
            accB = ffma2(dup2(wt), bt, accB);
        }
    }
    #pragma unroll
    for (int off = 8; off > 0; off >>= 1)
        wsum += __shfl_xor_sync(gmask, wsum, off, 16);
    float inv = 1.f / (wsum + 1e-16f);
    return make_float4(accA.x * inv, accA.y * inv, accB.x * inv, accB.y * inv);
}

// bias (permuted float4 channel order: 2l, 2l+32, 2l+1, 2l+33) + relu
__device__ __forceinline__ float4 bias_relu(float4 v, const float* __restrict__ bias, int lane16) {
    v.x = fmaxf(v.x + __ldg(&bias[2 * lane16]),      0.f);
    v.y = fmaxf(v.y + __ldg(&bias[2 * lane16 + 32]), 0.f);
    v.z = fmaxf(v.z + __ldg(&bias[2 * lane16 + 1]),  0.f);
    v.w = fmaxf(v.w + __ldg(&bias[2 * lane16 + 33]), 0.f);
    return v;
}

// ---------------- CSR: count ----------------
__global__ void count_kernel(const int* __restrict__ ei, int E) {
    int base = (blockIdx.x * blockDim.x + threadIdx.x) * 8;
    #pragma unroll
    for (int u = 0; u < 8; u++) {
        int i = base + u;
        if (i < E) atomicAdd(&g_deg[__ldg(&ei[E + i])], 1);
    }
}

// ---------------- parallel scan (2 kernels: sums, then offsets+write fused) ----
__global__ void scan_sums(int n) {
    __shared__ int ws[32];
    int b = blockIdx.x;
    int t = threadIdx.x, lane = t & 31, wid = t >> 5;
    int i = b * 1024 + t;
    int v = (i < n) ? g_deg[i] : 0;
    #pragma unroll
    for (int off = 16; off > 0; off >>= 1)
        v += __shfl_xor_sync(0xffffffffu, v, off);
    if (lane == 0) ws[wid] = v;
    __syncthreads();
    if (wid == 0) {
        int s = ws[lane];
        #pragma unroll
        for (int off = 16; off > 0; off >>= 1)
            s += __shfl_xor_sync(0xffffffffu, s, off);
        if (lane == 0) g_tsum[b] = s;
    }
}

__global__ void scan_write(int B, int n) {
    __shared__ int wsum[32];
    __shared__ int tbase;
    int b = blockIdx.x;
    int t = threadIdx.x, lane = t & 31, wid = t >> 5;
    if (t == 0) {
        int s = 0;
        for (int j = 0; j < b; j++) s += g_tsum[j];
        tbase = s;
        if (b == B - 1) g_rowptr[n] = s + g_tsum[B - 1];
    }
    __syncthreads();
    int i = b * 1024 + t;
    int v = (i < n) ? g_deg[i] : 0;
    int s = v;
    #pragma unroll
    for (int off = 1; off < 32; off <<= 1) {
        int u = __shfl_up_sync(0xffffffffu, s, off);
        if (lane >= off) s += u;
    }
    if (lane == 31) wsum[wid] = s;
    __syncthreads();
    if (wid == 0) {
        int ws = wsum[lane];
        #pragma unroll
        for (int off = 1; off < 32; off <<= 1) {
            int u = __shfl_up_sync(0xffffffffu, ws, off);
            if (lane >= off) ws += u;
        }
        wsum[lane] = ws;
    }
    __syncthreads();
    int woff = (wid > 0) ? wsum[wid - 1] : 0;
    int excl = tbase + woff + s - v;
    if (i < n) { g_rowptr[i] = excl; g_cnt[i] = excl; }
}

// ---------------- layer-0 GEMM + fused alpha + FUSED SCATTER ----------------
__global__ void gemm_alpha_kernel(const float4* __restrict__ X,
                                  const float* __restrict__ W,
                                  const float* __restrict__ a_src,
                                  const float* __restrict__ a_dst,
                                  __half2* __restrict__ hp_out,
                                  float* __restrict__ as_out,
                                  float* __restrict__ ad_out,
                                  int n, const int* __restrict__ ei, int E, int ggrid) {
    if (blockIdx.x >= ggrid) {
        int base = ((blockIdx.x - ggrid) * 256 + (threadIdx.y * 32 + threadIdx.x)) * 8;
        #pragma unroll
        for (int u = 0; u < 8; u++) {
            int i = base + u;
            if (i < E) {
                int src = __ldg(&ei[i]);
                int dst = __ldg(&ei[E + i]);
                int pos = atomicAdd(&g_cnt[dst], 1);
                g_esrc[pos] = src;
            }
        }
        return;
    }

    __shared__ float2 Ws2[CIN0 * 32];
    int tx = threadIdx.x, ty = threadIdx.y;
    int tid = ty * 32 + tx;
    for (int idx = tid; idx < CIN0 * 32; idx += 256) {
        int k = idx >> 5, c = idx & 31;
        Ws2[idx] = make_float2(W[k * 64 + c], W[k * 64 + c + 32]);
    }
    __syncthreads();

    int row0 = blockIdx.x * 32 + ty * 4;
    int r0 = min(row0 + 0, n - 1), r1 = min(row0 + 1, n - 1);
    int r2 = min(row0 + 2, n - 1), r3 = min(row0 + 3, n - 1);
    const float4* x0 = X + (size_t)r0 * 32;
    const float4* x1 = X + (size_t)r1 * 32;
    const float4* x2 = X + (size_t)r2 * 32;
    const float4* x3 = X + (size_t)r3 * 32;

    float2 acc0 = make_float2(0.f, 0.f), acc1 = make_float2(0.f, 0.f);
    float2 acc2 = make_float2(0.f, 0.f), acc3 = make_float2(0.f, 0.f);
    for (int k4 = 0; k4 < 32; k4++) {
        float4 v0 = x0[k4], v1 = x1[k4], v2 = x2[k4], v3 = x3[k4];
        int kb = k4 * 128 + tx;
        float2 wA = Ws2[kb], wB = Ws2[kb + 32], wC = Ws2[kb + 64], wD = Ws2[kb + 96];
        acc0 = ffma2(dup2(v0.x), wA, acc0); acc1 = ffma2(dup2(v1.x), wA, acc1);
        acc2 = ffma2(dup2(v2.x), wA, acc2); acc3 = ffma2(dup2(v3.x), wA, acc3);
        acc0 = ffma2(dup2(v0.y), wB, acc0); acc1 = ffma2(dup2(v1.y), wB, acc1);
        acc2 = ffma2(dup2(v2.y), wB, acc2); acc3 = ffma2(dup2(v3.y), wB, acc3);
        acc0 = ffma2(dup2(v0.z), wC, acc0); acc1 = ffma2(dup2(v1.z), wC, acc1);
        acc2 = ffma2(dup2(v2.z), wC, acc2); acc3 = ffma2(dup2(v3.z), wC, acc3);
        acc0 = ffma2(dup2(v0.w), wD, acc0); acc1 = ffma2(dup2(v1.w), wD, acc1);
        acc2 = ffma2(dup2(v2.w), wD, acc2); acc3 = ffma2(dup2(v3.w), wD, acc3);
    }

    if (row0 + 0 < n) hp_out[(size_t)(row0 + 0) * 32 + tx] = __float22half2_rn(acc0);
    if (row0 + 1 < n) hp_out[(size_t)(row0 + 1) * 32 + tx] = __float22half2_rn(acc1);
    if (row0 + 2 < n) hp_out[(size_t)(row0 + 2) * 32 + tx] = __float22half2_rn(acc2);
    if (row0 + 3 < n) hp_out[(size_t)(row0 + 3) * 32 + tx] = __float22half2_rn(acc3);

    float asA = __ldg(&a_src[tx]), asB = __ldg(&a_src[tx + 32]);
    float adA = __ldg(&a_dst[tx]), adB = __ldg(&a_dst[tx + 32]);
    float s0 = acc0.x * asA + acc0.y * asB, s1 = acc1.x * asA + acc1.y * asB;
    float s2 = acc2.x * asA + acc2.y * asB, s3 = acc3.x * asA + acc3.y * asB;
    float d0 = acc0.x * adA + acc0.y * adB, d1 = acc1.x * adA + acc1.y * adB;
    float d2 = acc2.x * adA + acc2.y * adB, d3 = acc3.x * adA + acc3.y * adB;
    #pragma unroll
    for (int off = 16; off > 0; off >>= 1) {
        s0 += __shfl_xor_sync(0xffffffffu, s0, off); s1 += __shfl_xor_sync(0xffffffffu, s1, off);
        s2 += __shfl_xor_sync(0xffffffffu, s2, off); s3 += __shfl_xor_sync(0xffffffffu, s3, off);
        d0 += __shfl_xor_sync(0xffffffffu, d0, off); d1 += __shfl_xor_sync(0xffffffffu, d1, off);
        d2 += __shfl_xor_sync(0xffffffffu, d2, off); d3 += __shfl_xor_sync(0xffffffffu, d3, off);
    }
    if (tx == 0) {
        if (row0 + 0 < n) { as_out[row0 + 0] = s0; ad_out[row0 + 0] = d0; }
        if (row0 + 1 < n) { as_out[row0 + 1] = s1; ad_out[row0 + 1] = d1; }
        if (row0 + 2 < n) { as_out[row0 + 2] = s2; ad_out[row0 + 2] = d2; }
        if (row0 + 3 < n) { as_out[row0 + 3] = s3; ad_out[row0 + 3] = d3; }
    }
}

// ---------------- fused: aggregate(prev) -> smem -> WMMA GEMM + alpha (next) ----
__global__ void __launch_bounds__(256, 6)
agg_gemm_kernel(const __half2* __restrict__ hp_in,
                const float* __restrict__ as_in, const float* __restrict__ ad_in,
                const float* __restrict__ bias,
                const float* __restrict__ W,
                const float* __restrict__ a_src, const float* __restrict__ a_dst,
                __half2* __restrict__ hp_out,
                float* __restrict__ as_out, float* __restrict__ ad_out, int n) {
    __shared__ __align__(32) __half  As[32 * 64];    // 4 KB aggregated h, PHYSICAL order
    __shared__ __align__(32) __half  WsH[64 * 64];   // 8 KB fp16 weights, row-major
    __shared__ __align__(32) float   Cs[32 * 64];    // 8 KB GEMM output
    __shared__ __align__(16) float2  Pairs[16][16];  // 2 KB (w,src) staging

    int tid = threadIdx.x;
    int warp = tid >> 5, lane = tid & 31;
    int g = lane >> 4, lane16 = lane & 15;
    unsigned gmask = 0xFFFFu << (g << 4);
    int node0 = blockIdx.x * 32;
    float2* pairs = Pairs[warp * 2 + g];

    for (int idx = tid; idx < 64 * 64; idx += 256)
        WsH[idx] = __float2half(W[idx]);

    // aggregate phase: warp -> 4 nodes, two per pass (one per 16-lane group)
    #pragma unroll
    for (int r = 0; r < 2; r++) {
        int node = node0 + warp * 4 + r * 2 + g;
        float4 v = make_float4(0.f, 0.f, 0.f, 0.f);
        if (node < n) {
            int start = g_rowptr[node];
            int end   = g_rowptr[node + 1];
            float ad_n = __ldg(&ad_in[node]);
            int j0 = start + lane16, j1 = j0 + 16;
            int s0 = 0, s1 = 0;
            if (j0 < end) s0 = __ldg(&g_esrc[j0]);
            if (j1 < end) s1 = __ldg(&g_esrc[j1]);
            float a0 = (j0 < end) ? __ldg(&as_in[s0]) : 0.f;
            float a1 = (j1 < end) ? __ldg(&as_in[s1]) : 0.f;
            float w_self = __expf(leaky(__ldg(&as_in[node]) + ad_n));
            uint2 vsr = hp_row16(hp_in, node, lane16);
            v = agg_body(gmask, pairs, hp_in, as_in, start, end, ad_n, w_self,
                         vsr, s0, s1, a0, a1, lane16);
            v = bias_relu(v, bias, lane16);
        }
        // store h to As in PHYSICAL channel order: v = ch (2l, 2l+32, 2l+1, 2l+33)
        int i = warp * 4 + r * 2 + g;
        __half2* rowp = (__half2*)&As[i * 64];
        rowp[lane16]      = __floats2half2_rn(v.x, v.z);   // ch 2l, 2l+1
        rowp[lane16 + 16] = __floats2half2_rn(v.y, v.w);   // ch 2l+32, 2l+33
    }
    __syncthreads();

    // ---- WMMA GEMM: C[32x64] = A[32x64] x W[64x64], fp16 in / fp32 acc ----
    {
        int m_tile = warp & 1;        // 2 tiles of 16 rows
        int n_tile = warp >> 1;       // 4 tiles of 16 cols
        wmma::fragment<wmma::matrix_a, 16, 16, 16, __half, wmma::row_major> fa;
        wmma::fragment<wmma::matrix_b, 16, 16, 16, __half, wmma::row_major> fb;
        wmma::fragment<wmma::accumulator, 16, 16, 16, float> fc;
        wmma::fill_fragment(fc, 0.f);
        #pragma unroll
        for (int k0 = 0; k0 < 64; k0 += 16) {
            wmma::load_matrix_sync(fa, &As[(m_tile * 16) * 64 + k0], 64);
            wmma::load_matrix_sync(fb, &WsH[k0 * 64 + n_tile * 16], 64);
            wmma::mma_sync(fc, fa, fb, fc);
        }
        wmma::store_matrix_sync(&Cs[(m_tile * 16) * 64 + n_tile * 16], fc, 64,
                                wmma::mem_row_major);
    }
    __syncthreads();

    // ---- epilogue: hp_out (permuted half2) + alpha from Cs ----
    int tx = lane, ty = warp;
    int row0 = node0 + ty * 4;
    float c0r0 = Cs[(ty * 4 + 0) * 64 + tx], c1r0 = Cs[(ty * 4 + 0) * 64 + tx + 32];
    float c0r1 = Cs[(ty * 4 + 1) * 64 + tx], c1r1 = Cs[(ty * 4 + 1) * 64 + tx + 32];
    float c0r2 = Cs[(ty * 4 + 2) * 64 + tx], c1r2 = Cs[(ty * 4 + 2) * 64 + tx + 32];
    float c0r3 = Cs[(ty * 4 + 3) * 64 + tx], c1r3 = Cs[(ty * 4 + 3) * 64 + tx + 32];

    if (row0 + 0 < n) hp_out[(size_t)(row0 + 0) * 32 + tx] = __floats2half2_rn(c0r0, c1r0);
    if (row0 + 1 < n) hp_out[(size_t)(row0 + 1) * 32 + tx] = __floats2half2_rn(c0r1, c1r1);
    if (row0 + 2 < n) hp_out[(size_t)(row0 + 2) * 32 + tx] = __floats2half2_rn(c0r2, c1r2);
    if (row0 + 3 < n) hp_out[(size_t)(row0 + 3) * 32 + tx] = __floats2half2_rn(c0r3, c1r3);

    float asA = __ldg(&a_src[tx]), asB = __ldg(&a_src[tx + 32]);
    float adA = __ldg(&a_dst[tx]), adB = __ldg(&a_dst[tx + 32]);
    float s0 = c0r0 * asA + c1r0 * asB, s1 = c0r1 * asA + c1r1 * asB;
    float s2 = c0r2 * asA + c1r2 * asB, s3 = c0r3 * asA + c1r3 * asB;
    float d0 = c0r0 * adA + c1r0 * adB, d1 = c0r1 * adA + c1r1 * adB;
    float d2 = c0r2 * adA + c1r2 * adB, d3 = c0r3 * adA + c1r3 * adB;
    #pragma unroll
    for (int off = 16; off > 0; off >>= 1) {
        s0 += __shfl_xor_sync(0xffffffffu, s0, off); s1 += __shfl_xor_sync(0xffffffffu, s1, off);
        s2 += __shfl_xor_sync(0xffffffffu, s2, off); s3 += __shfl_xor_sync(0xffffffffu, s3, off);
        d0 += __shfl_xor_sync(0xffffffffu, d0, off); d1 += __shfl_xor_sync(0xffffffffu, d1, off);
        d2 += __shfl_xor_sync(0xffffffffu, d2, off); d3 += __shfl_xor_sync(0xffffffffu, d3, off);
    }
    if (tx == 0) {
        if (row0 + 0 < n) { as_out[row0 + 0] = s0; ad_out[row0 + 0] = d0; }
        if (row0 + 1 < n) { as_out[row0 + 1] = s1; ad_out[row0 + 1] = d1; }
        if (row0 + 2 < n) { as_out[row0 + 2] = s2; ad_out[row0 + 2] = d2; }
        if (row0 + 3 < n) { as_out[row0 + 3] = s3; ad_out[row0 + 3] = d3; }
    }
}

// ---------------- final aggregate -> external output (32 nodes/block) ----------------
__global__ void __launch_bounds__(256, 6)
agg_out_kernel(const __half2* __restrict__ hp_in,
               const float* __restrict__ as_in, const float* __restrict__ ad_in,
               const float* __restrict__ bias, float* __restrict__ out, int n) {
    __shared__ __align__(16) float2 Pairs[16][16];
    int tid = threadIdx.x;
    int warp = tid >> 5, lane = tid & 31;
    int g = lane >> 4, lane16 = lane & 15;
    unsigned gmask = 0xFFFFu << (g << 4);
    float2* pairs = Pairs[warp * 2 + g];
    int node0 = blockIdx.x * 32;
    #pragma unroll
    for (int r = 0; r < 2; r++) {
        int node = node0 + warp * 4 + r * 2 + g;
        if (node >= n) continue;
        int start = g_rowptr[node];
        int end   = g_rowptr[node + 1];
        float ad_n = __ldg(&ad_in[node]);
        int j0 = start + lane16, j1 = j0 + 16;
        int s0 = 0, s1 = 0;
        if (j0 < end) s0 = __ldg(&g_esrc[j0]);
        if (j1 < end) s1 = __ldg(&g_esrc[j1]);
        float a0 = (j0 < end) ? __ldg(&as_in[s0]) : 0.f;
        float a1 = (j1 < end) ? __ldg(&as_in[s1]) : 0.f;
        float w_self = __expf(leaky(__ldg(&as_in[node]) + ad_n));
        uint2 vsr = hp_row16(hp_in, node, lane16);
        float4 v = agg_body(gmask, pairs, hp_in, as_in, start, end, ad_n, w_self,
                            vsr, s0, s1, a0, a1, lane16);
        v = bias_relu(v, bias, lane16);
        float* o = out + (size_t)node * 64;
        ((float2*)o)[lane16]        = make_float2(v.x, v.z);   // ch 2l, 2l+1
        ((float2*)(o + 32))[lane16] = make_float2(v.y, v.w);   // ch 2l+32, 2l+33
    }
}

// ---------------- host launcher ----------------
extern "C" void kernel_launch(void* const* d_in, const int* in_sizes, int n_in,
                              void* d_out, int out_size) {
    const float* x  = (const float*)d_in[0];
    const int*   ei = (const int*)  d_in[1];
    const float* W0 = (const float*)d_in[4];
    const float* av_s0 = (const float*)d_in[5];
    const float* av_d0 = (const float*)d_in[6];
    const float* b0  = (const float*)d_in[7];
    const float* W1 = (const float*)d_in[8];
    const float* av_s1 = (const float*)d_in[9];
    const float* av_d1 = (const float*)d_in[10];
    const float* b1  = (const float*)d_in[11];
    const float* W2 = (const float*)d_in[12];
    const float* av_s2 = (const float*)d_in[13];
    const float* av_d2 = (const float*)d_in[14];
    const float* b2  = (const float*)d_in[15];

    int n = in_sizes[0] / CIN0;
    int E = in_sizes[1] / 2;
    float* out = (float*)d_out;

    void *degp, *hpA, *hpB, *asA, *adA, *asB, *adB;
    cudaGetSymbolAddress(&degp, g_deg);
    cudaGetSymbolAddress(&hpA, g_hpA);
    cudaGetSymbolAddress(&hpB, g_hpB);
    cudaGetSymbolAddress(&asA, g_asA);
    cudaGetSymbolAddress(&adA, g_adA);
    cudaGetSymbolAddress(&asB, g_asB);
    cudaGetSymbolAddress(&adB, g_adB);

    cudaMemsetAsync(degp, 0, (size_t)n * sizeof(int), 0);

    dim3 gblock(32, 8);
    int ggrid = (n + 31) / 32;
    int sgrid = (E + 2047) / 2048;          // scatter blocks (fused into gemm_alpha)
    int tiles = (n + 1023) / 1024;          // scan tiles (<= 64)

    // CSR: count -> parallel scan (2 kernels)
    count_kernel<<<(E + 2047) / 2048, 256>>>(ei, E);
    scan_sums   <<<tiles, 1024>>>(n);
    scan_write  <<<tiles, 1024>>>(tiles, n);

    // layer 0: GEMM(x,W0)+alpha0 -> buf A   (+ fused scatter, overlapping)
    gemm_alpha_kernel<<<ggrid + sgrid, gblock>>>((const float4*)x, W0, av_s0, av_d0,
                                                 (__half2*)hpA, (float*)asA, (float*)adA,
                                                 n, ei, E, ggrid);

    // agg(L0, A) + WMMA GEMM(W1) + alpha1 -> buf B
    agg_gemm_kernel<<<ggrid, 256>>>((const __half2*)hpA, (const float*)asA, (const float*)adA,
                                    b0, W1, av_s1, av_d1,
                                    (__half2*)hpB, (float*)asB, (float*)adB, n);
    // agg(L1, B) + WMMA GEMM(W2) + alpha2 -> buf A
    agg_gemm_kernel<<<ggrid, 256>>>((const __half2*)hpB, (const float*)asB, (const float*)adB,
                                    b1, W2, av_s2, av_d2,
                                    (__half2*)hpA, (float*)asA, (float*)adA, n);
    // final aggregate -> out (32 nodes/block)
    agg_out_kernel<<<(n + 31) / 32, 256>>>((const __half2*)hpA, (const float*)asA,
                                           (const float*)adA, b2, out, n);
}

// round 17
// speedup vs baseline: 1.1072x; 1.1072x over previous
#include <cuda_runtime.h>
#include <cuda_fp16.h>
#include <math.h>

#define MAXN 50000
#define MAXE 800000
#define CIN0 128
#define COUT 64
#define NEG_SLOPE 0.2f

// ---------------- device scratch (double-buffered) ----------------
// hp stored fp16, PERMUTED: position p = half2(channel p, channel p+32); row = 128B
__device__ __half2 g_hpA[MAXN * 32];
__device__ __half2 g_hpB[MAXN * 32];
__device__ float   g_asA[MAXN], g_adA[MAXN];
__device__ float   g_asB[MAXN], g_adB[MAXN];
__device__ int     g_rowptr[MAXN + 1];
__device__ int     g_deg[MAXN];
__device__ int     g_cnt[MAXN];
__device__ int     g_esrc[MAXE];
__device__ int     g_tsum[64];

// ---------------- packed f32x2 helpers ----------------
__device__ __forceinline__ float2 ffma2(float2 a, float2 b, float2 c) {
    unsigned long long ra = *(unsigned long long*)&a;
    unsigned long long rb = *(unsigned long long*)&b;
    unsigned long long rc = *(unsigned long long*)&c;
    unsigned long long rd;
    asm("fma.rn.f32x2 %0, %1, %2, %3;" : "=l"(rd) : "l"(ra), "l"(rb), "l"(rc));
    return *(float2*)&rd;
}
__device__ __forceinline__ float2 dup2(float x) { return make_float2(x, x); }
__device__ __forceinline__ float leaky(float e) { return e > 0.f ? e : NEG_SLOPE * e; }

// fp16 hp row accessor: row = 128 bytes; lane16 owns 8B (channels 2l,2l+32,2l+1,2l+33)
__device__ __forceinline__ uint2 hp_row16(const __half2* hp, int i, int lane16) {
    return *((const uint2*)((const char*)hp + ((unsigned)i << 7)) + lane16);
}
__device__ __forceinline__ void unpack_hp(uint2 r, float2& f0, float2& f1) {
    f0 = __half22float2(*(const __half2*)&r.x);
    f1 = __half22float2(*(const __half2*)&r.y);
}

// ---------------- 16-lane gather via smem (w,src) pairs; LDS.128 = 2 edges ----
__device__ __forceinline__ void gather16s(unsigned gmask, float2* pairs,
                                          float w, int src, int cnt, int lane16,
                                          const __half2* __restrict__ hp,
                                          float2& accA, float2& accB) {
    __syncwarp(gmask);
    pairs[lane16] = make_float2(w, __int_as_float(src));
    __syncwarp(gmask);
    int cnt_r = (cnt + 3) & ~3;        // zero-padded: safe to over-read
    for (int t = 0; t < cnt_r; t += 4) {
        float4 p01 = *(const float4*)&pairs[t];
        float4 p23 = *(const float4*)&pairs[t + 2];
        int i0 = __float_as_int(p01.y), i1 = __float_as_int(p01.w);
        int i2 = __float_as_int(p23.y), i3 = __float_as_int(p23.w);
        uint2 r0 = hp_row16(hp, i0, lane16);
        uint2 r1 = hp_row16(hp, i1, lane16);
        uint2 r2 = hp_row16(hp, i2, lane16);
        uint2 r3 = hp_row16(hp, i3, lane16);
        float2 a0, b0, a1, b1, a2, b2, a3, b3;
        unpack_hp(r0, a0, b0);
        unpack_hp(r1, a1, b1);
        unpack_hp(r2, a2, b2);
        unpack_hp(r3, a3, b3);
        accA = ffma2(dup2(p01.x), a0, accA); accB = ffma2(dup2(p01.x), b0, accB);
        accA = ffma2(dup2(p01.z), a1, accA); accB = ffma2(dup2(p01.z), b1, accB);
        accA = ffma2(dup2(p23.x), a2, accA); accB = ffma2(dup2(p23.x), b2, accB);
        accA = ffma2(dup2(p23.z), a3, accA); accB = ffma2(dup2(p23.z), b3, accB);
    }
}

// gather + normalize for one node given pre-fetched front data
__device__ __forceinline__ float4 agg_body(unsigned gmask, float2* pairs,
                                           const __half2* __restrict__ hp,
                                           const float* __restrict__ as,
                                           int start, int end, float ad_n, float w_self,
                                           uint2 vsr, int s0, int s1, float a0, float a1,
                                           int lane16) {
    int j0 = start + lane16, j1 = j0 + 16;
    float w0 = (j0 < end) ? __expf(leaky(a0 + ad_n)) : 0.f;
    float w1 = (j1 < end) ? __expf(leaky(a1 + ad_n)) : 0.f;
    int   sj0 = (j0 < end) ? s0 : 0;
    int   sj1 = (j1 < end) ? s1 : 0;
    float wsum = w0 + w1 + ((lane16 == 0) ? w_self : 0.f);
    float2 vsA, vsB;
    unpack_hp(vsr, vsA, vsB);
    float2 accA = make_float2(w_self * vsA.x, w_self * vsA.y);
    float2 accB = make_float2(w_self * vsB.x, w_self * vsB.y);
    int deg = end - start;
    if (deg > 0)  gather16s(gmask, pairs, w0, sj0, min(16, deg),      lane16, hp, accA, accB);
    if (deg > 16) gather16s(gmask, pairs, w1, sj1, min(16, deg - 16), lane16, hp, accA, accB);
    for (int jb = start + 32; jb < end; jb += 16) {   // rare: deg > 32 (shfl path)
        int jj = jb + lane16;
        int cnt = min(16, end - jb);
        int sj = 0; float w = 0.f;
        if (jj < end) {
            sj = __ldg(&g_esrc[jj]);
            w = __expf(leaky(__ldg(&as[sj]) + ad_n));
        }
        wsum += w;
        for (int t = 0; t < cnt; t++) {
            float wt = __shfl_sync(gmask, w, t, 16);
            int   it = __shfl_sync(gmask, sj, t, 16);
            uint2 rt = hp_row16(hp, it, lane16);
            float2 at, bt;
            unpack_hp(rt, at, bt);
            accA = ffma2(dup2(wt), at, accA);
            accB = ffma2(dup2(wt), bt, accB);
        }
    }
    #pragma unroll
    for (int off = 8; off > 0; off >>= 1)
        wsum += __shfl_xor_sync(gmask, wsum, off, 16);
    float inv = 1.f / (wsum + 1e-16f);
    return make_float4(accA.x * inv, accA.y * inv, accB.x * inv, accB.y * inv);
}

// bias (permuted float4 channel order: 2l, 2l+32, 2l+1, 2l+33) + relu
__device__ __forceinline__ float4 bias_relu(float4 v, const float* __restrict__ bias, int lane16) {
    v.x = fmaxf(v.x + __ldg(&bias[2 * lane16]),      0.f);
    v.y = fmaxf(v.y + __ldg(&bias[2 * lane16 + 32]), 0.f);
    v.z = fmaxf(v.z + __ldg(&bias[2 * lane16 + 1]),  0.f);
    v.w = fmaxf(v.w + __ldg(&bias[2 * lane16 + 33]), 0.f);
    return v;
}

// ---------------- CSR: count ----------------
__global__ void count_kernel(const int* __restrict__ ei, int E) {
    int base = (blockIdx.x * blockDim.x + threadIdx.x) * 8;
    #pragma unroll
    for (int u = 0; u < 8; u++) {
        int i = base + u;
        if (i < E) atomicAdd(&g_deg[__ldg(&ei[E + i])], 1);
    }
}

// ---------------- parallel scan (sums, then offsets+write fused) ----------------
__global__ void scan_sums(int n) {
    __shared__ int ws[32];
    int b = blockIdx.x;
    int t = threadIdx.x, lane = t & 31, wid = t >> 5;
    int i = b * 1024 + t;
    int v = (i < n) ? g_deg[i] : 0;
    #pragma unroll
    for (int off = 16; off > 0; off >>= 1)
        v += __shfl_xor_sync(0xffffffffu, v, off);
    if (lane == 0) ws[wid] = v;
    __syncthreads();
    if (wid == 0) {
        int s = ws[lane];
        #pragma unroll
        for (int off = 16; off > 0; off >>= 1)
            s += __shfl_xor_sync(0xffffffffu, s, off);
        if (lane == 0) g_tsum[b] = s;
    }
}

__global__ void scan_write(int B, int n) {
    __shared__ int wsum[32];
    __shared__ int tbase;
    int b = blockIdx.x;
    int t = threadIdx.x, lane = t & 31, wid = t >> 5;
    if (t == 0) {
        int s = 0;
        for (int j = 0; j < b; j++) s += g_tsum[j];
        tbase = s;
        if (b == B - 1) g_rowptr[n] = s + g_tsum[B - 1];
    }
    __syncthreads();
    int i = b * 1024 + t;
    int v = (i < n) ? g_deg[i] : 0;
    int s = v;
    #pragma unroll
    for (int off = 1; off < 32; off <<= 1) {
        int u = __shfl_up_sync(0xffffffffu, s, off);
        if (lane >= off) s += u;
    }
    if (lane == 31) wsum[wid] = s;
    __syncthreads();
    if (wid == 0) {
        int ws = wsum[lane];
        #pragma unroll
        for (int off = 1; off < 32; off <<= 1) {
            int u = __shfl_up_sync(0xffffffffu, ws, off);
            if (lane >= off) ws += u;
        }
        wsum[lane] = ws;
    }
    __syncthreads();
    int woff = (wid > 0) ? wsum[wid - 1] : 0;
    int excl = tbase + woff + s - v;
    if (i < n) { g_rowptr[i] = excl; g_cnt[i] = excl; }
}

__global__ void scatter_kernel(const int* __restrict__ ei, int E) {
    int base = (blockIdx.x * blockDim.x + threadIdx.x) * 8;
    #pragma unroll
    for (int u = 0; u < 8; u++) {
        int i = base + u;
        if (i < E) {
            int src = __ldg(&ei[i]);
            int dst = __ldg(&ei[E + i]);
            int pos = atomicAdd(&g_cnt[dst], 1);
            g_esrc[pos] = src;
        }
    }
}

// ---------------- layer-0 GEMM + fused alpha (pure; runs on side stream) --------
__global__ void gemm_alpha_kernel(const float4* __restrict__ X,
                                  const float* __restrict__ W,
                                  const float* __restrict__ a_src,
                                  const float* __restrict__ a_dst,
                                  __half2* __restrict__ hp_out,
                                  float* __restrict__ as_out,
                                  float* __restrict__ ad_out, int n) {
    __shared__ float2 Ws2[CIN0 * 32];
    int tx = threadIdx.x, ty = threadIdx.y;
    int tid = ty * 32 + tx;
    for (int idx = tid; idx < CIN0 * 32; idx += 256) {
        int k = idx >> 5, c = idx & 31;
        Ws2[idx] = make_float2(W[k * 64 + c], W[k * 64 + c + 32]);
    }
    __syncthreads();

    int row0 = blockIdx.x * 32 + ty * 4;
    int r0 = min(row0 + 0, n - 1), r1 = min(row0 + 1, n - 1);
    int r2 = min(row0 + 2, n - 1), r3 = min(row0 + 3, n - 1);
    const float4* x0 = X + (size_t)r0 * 32;
    const float4* x1 = X + (size_t)r1 * 32;
    const float4* x2 = X + (size_t)r2 * 32;
    const float4* x3 = X + (size_t)r3 * 32;

    float2 acc0 = make_float2(0.f, 0.f), acc1 = make_float2(0.f, 0.f);
    float2 acc2 = make_float2(0.f, 0.f), acc3 = make_float2(0.f, 0.f);
    for (int k4 = 0; k4 < 32; k4++) {
        float4 v0 = x0[k4], v1 = x1[k4], v2 = x2[k4], v3 = x3[k4];
        int kb = k4 * 128 + tx;
        float2 wA = Ws2[kb], wB = Ws2[kb + 32], wC = Ws2[kb + 64], wD = Ws2[kb + 96];
        acc0 = ffma2(dup2(v0.x), wA, acc0); acc1 = ffma2(dup2(v1.x), wA, acc1);
        acc2 = ffma2(dup2(v2.x), wA, acc2); acc3 = ffma2(dup2(v3.x), wA, acc3);
        acc0 = ffma2(dup2(v0.y), wB, acc0); acc1 = ffma2(dup2(v1.y), wB, acc1);
        acc2 = ffma2(dup2(v2.y), wB, acc2); acc3 = ffma2(dup2(v3.y), wB, acc3);
        acc0 = ffma2(dup2(v0.z), wC, acc0); acc1 = ffma2(dup2(v1.z), wC, acc1);
        acc2 = ffma2(dup2(v2.z), wC, acc2); acc3 = ffma2(dup2(v3.z), wC, acc3);
        acc0 = ffma2(dup2(v0.w), wD, acc0); acc1 = ffma2(dup2(v1.w), wD, acc1);
        acc2 = ffma2(dup2(v2.w), wD, acc2); acc3 = ffma2(dup2(v3.w), wD, acc3);
    }

    if (row0 + 0 < n) hp_out[(size_t)(row0 + 0) * 32 + tx] = __float22half2_rn(acc0);
    if (row0 + 1 < n) hp_out[(size_t)(row0 + 1) * 32 + tx] = __float22half2_rn(acc1);
    if (row0 + 2 < n) hp_out[(size_t)(row0 + 2) * 32 + tx] = __float22half2_rn(acc2);
    if (row0 + 3 < n) hp_out[(size_t)(row0 + 3) * 32 + tx] = __float22half2_rn(acc3);

    float asA = __ldg(&a_src[tx]), asB = __ldg(&a_src[tx + 32]);
    float adA = __ldg(&a_dst[tx]), adB = __ldg(&a_dst[tx + 32]);
    float s0 = acc0.x * asA + acc0.y * asB, s1 = acc1.x * asA + acc1.y * asB;
    float s2 = acc2.x * asA + acc2.y * asB, s3 = acc3.x * asA + acc3.y * asB;
    float d0 = acc0.x * adA + acc0.y * adB, d1 = acc1.x * adA + acc1.y * adB;
    float d2 = acc2.x * adA + acc2.y * adB, d3 = acc3.x * adA + acc3.y * adB;
    #pragma unroll
    for (int off = 16; off > 0; off >>= 1) {
        s0 += __shfl_xor_sync(0xffffffffu, s0, off); s1 += __shfl_xor_sync(0xffffffffu, s1, off);
        s2 += __shfl_xor_sync(0xffffffffu, s2, off); s3 += __shfl_xor_sync(0xffffffffu, s3, off);
        d0 += __shfl_xor_sync(0xffffffffu, d0, off); d1 += __shfl_xor_sync(0xffffffffu, d1, off);
        d2 += __shfl_xor_sync(0xffffffffu, d2, off); d3 += __shfl_xor_sync(0xffffffffu, d3, off);
    }
    if (tx == 0) {
        if (row0 + 0 < n) { as_out[row0 + 0] = s0; ad_out[row0 + 0] = d0; }
        if (row0 + 1 < n) { as_out[row0 + 1] = s1; ad_out[row0 + 1] = d1; }
        if (row0 + 2 < n) { as_out[row0 + 2] = s2; ad_out[row0 + 2] = d2; }
        if (row0 + 3 < n) { as_out[row0 + 3] = s3; ad_out[row0 + 3] = d3; }
    }
}

// ---------------- fused: aggregate(prev) -> smem -> GEMM + alpha (next) ----------------
__global__ void __launch_bounds__(256, 6)
agg_gemm_kernel(const __half2* __restrict__ hp_in,
                const float* __restrict__ as_in, const float* __restrict__ ad_in,
                const float* __restrict__ bias,
                const float* __restrict__ W,
                const float* __restrict__ a_src, const float* __restrict__ a_dst,
                __half2* __restrict__ hp_out,
                float* __restrict__ as_out, float* __restrict__ ad_out, int n) {
    __shared__ float2 Ws2[COUT * 32];                 // 16 KB
    __shared__ float4 Hs4[32 * 16];                   //  8 KB
    __shared__ __align__(16) float2 Pairs[16][16];    //  2 KB (w,src) staging

    int tid = threadIdx.x;
    int warp = tid >> 5, lane = tid & 31;
    int g = lane >> 4, lane16 = lane & 15;
    unsigned gmask = 0xFFFFu << (g << 4);
    int node0 = blockIdx.x * 32;
    float2* pairs = Pairs[warp * 2 + g];

    for (int idx = tid; idx < COUT * 32; idx += 256) {
        int k = idx >> 5, c = idx & 31;
        int kk = (k >> 1) + ((k & 1) << 5);
        Ws2[idx] = make_float2(W[kk * 64 + c], W[kk * 64 + c + 32]);
    }

    // aggregate phase: warp -> 4 nodes, two per pass (one per 16-lane group)
    #pragma unroll
    for (int r = 0; r < 2; r++) {
        int node = node0 + warp * 4 + r * 2 + g;
        float4 v = make_float4(0.f, 0.f, 0.f, 0.f);
        if (node < n) {
            int start = g_rowptr[node];
            int end   = g_rowptr[node + 1];
            float ad_n = __ldg(&ad_in[node]);
            int j0 = start + lane16, j1 = j0 + 16;
            int s0 = 0, s1 = 0;
            if (j0 < end) s0 = __ldg(&g_esrc[j0]);
            if (j1 < end) s1 = __ldg(&g_esrc[j1]);
            float a0 = (j0 < end) ? __ldg(&as_in[s0]) : 0.f;
            float a1 = (j1 < end) ? __ldg(&as_in[s1]) : 0.f;
            float w_self = __expf(leaky(__ldg(&as_in[node]) + ad_n));
            uint2 vsr = hp_row16(hp_in, node, lane16);
            v = agg_body(gmask, pairs, hp_in, as_in, start, end, ad_n, w_self,
                         vsr, s0, s1, a0, a1, lane16);
            v = bias_relu(v, bias, lane16);
        }
        Hs4[(warp * 4 + r * 2 + g) * 16 + lane16] = v;
    }
    __syncthreads();

    // GEMM phase (fp32 from smem)
    int tx = lane, ty = warp;
    int row0 = node0 + ty * 4;
    const float4* x0 = &Hs4[(ty * 4 + 0) * 16];
    const float4* x1 = &Hs4[(ty * 4 + 1) * 16];
    const float4* x2 = &Hs4[(ty * 4 + 2) * 16];
    const float4* x3 = &Hs4[(ty * 4 + 3) * 16];

    float2 acc0 = make_float2(0.f, 0.f), acc1 = make_float2(0.f, 0.f);
    float2 acc2 = make_float2(0.f, 0.f), acc3 = make_float2(0.f, 0.f);
    #pragma unroll 4
    for (int k4 = 0; k4 < 16; k4++) {
        float4 v0 = x0[k4], v1 = x1[k4], v2 = x2[k4], v3 = x3[k4];
        int kb = k4 * 128 + tx;
        float2 wA = Ws2[kb], wB = Ws2[kb + 32], wC = Ws2[kb + 64], wD = Ws2[kb + 96];
        acc0 = ffma2(dup2(v0.x), wA, acc0); acc1 = ffma2(dup2(v1.x), wA, acc1);
        acc2 = ffma2(dup2(v2.x), wA, acc2); acc3 = ffma2(dup2(v3.x), wA, acc3);
        acc0 = ffma2(dup2(v0.y), wB, acc0); acc1 = ffma2(dup2(v1.y), wB, acc1);
        acc2 = ffma2(dup2(v2.y), wB, acc2); acc3 = ffma2(dup2(v3.y), wB, acc3);
        acc0 = ffma2(dup2(v0.z), wC, acc0); acc1 = ffma2(dup2(v1.z), wC, acc1);
        acc2 = ffma2(dup2(v2.z), wC, acc2); acc3 = ffma2(dup2(v3.z), wC, acc3);
        acc0 = ffma2(dup2(v0.w), wD, acc0); acc1 = ffma2(dup2(v1.w), wD, acc1);
        acc2 = ffma2(dup2(v2.w), wD, acc2); acc3 = ffma2(dup2(v3.w), wD, acc3);
    }

    if (row0 + 0 < n) hp_out[(size_t)(row0 + 0) * 32 + tx] = __float22half2_rn(acc0);
    if (row0 + 1 < n) hp_out[(size_t)(row0 + 1) * 32 + tx] = __float22half2_rn(acc1);
    if (row0 + 2 < n) hp_out[(size_t)(row0 + 2) * 32 + tx] = __float22half2_rn(acc2);
    if (row0 + 3 < n) hp_out[(size_t)(row0 + 3) * 32 + tx] = __float22half2_rn(acc3);

    float asA = __ldg(&a_src[tx]), asB = __ldg(&a_src[tx + 32]);
    float adA = __ldg(&a_dst[tx]), adB = __ldg(&a_dst[tx + 32]);
    float s0 = acc0.x * asA + acc0.y * asB, s1 = acc1.x * asA + acc1.y * asB;
    float s2 = acc2.x * asA + acc2.y * asB, s3 = acc3.x * asA + acc3.y * asB;
    float d0 = acc0.x * adA + acc0.y * adB, d1 = acc1.x * adA + acc1.y * adB;
    float d2 = acc2.x * adA + acc2.y * adB, d3 = acc3.x * adA + acc3.y * adB;
    #pragma unroll
    for (int off = 16; off > 0; off >>= 1) {
        s0 += __shfl_xor_sync(0xffffffffu, s0, off); s1 += __shfl_xor_sync(0xffffffffu, s1, off);
        s2 += __shfl_xor_sync(0xffffffffu, s2, off); s3 += __shfl_xor_sync(0xffffffffu, s3, off);
        d0 += __shfl_xor_sync(0xffffffffu, d0, off); d1 += __shfl_xor_sync(0xffffffffu, d1, off);
        d2 += __shfl_xor_sync(0xffffffffu, d2, off); d3 += __shfl_xor_sync(0xffffffffu, d3, off);
    }
    if (tx == 0) {
        if (row0 + 0 < n) { as_out[row0 + 0] = s0; ad_out[row0 + 0] = d0; }
        if (row0 + 1 < n) { as_out[row0 + 1] = s1; ad_out[row0 + 1] = d1; }
        if (row0 + 2 < n) { as_out[row0 + 2] = s2; ad_out[row0 + 2] = d2; }
        if (row0 + 3 < n) { as_out[row0 + 3] = s3; ad_out[row0 + 3] = d3; }
    }
}

// ---------------- final aggregate -> external output (32 nodes/block) ----------------
__global__ void __launch_bounds__(256, 6)
agg_out_kernel(const __half2* __restrict__ hp_in,
               const float* __restrict__ as_in, const float* __restrict__ ad_in,
               const float* __restrict__ bias, float* __restrict__ out, int n) {
    __shared__ __align__(16) float2 Pairs[16][16];
    int tid = threadIdx.x;
    int warp = tid >> 5, lane = tid & 31;
    int g = lane >> 4, lane16 = lane & 15;
    unsigned gmask = 0xFFFFu << (g << 4);
    float2* pairs = Pairs[warp * 2 + g];
    int node0 = blockIdx.x * 32;
    #pragma unroll
    for (int r = 0; r < 2; r++) {
        int node = node0 + warp * 4 + r * 2 + g;
        if (node >= n) continue;
        int start = g_rowptr[node];
        int end   = g_rowptr[node + 1];
        float ad_n = __ldg(&ad_in[node]);
        int j0 = start + lane16, j1 = j0 + 16;
        int s0 = 0, s1 = 0;
        if (j0 < end) s0 = __ldg(&g_esrc[j0]);
        if (j1 < end) s1 = __ldg(&g_esrc[j1]);
        float a0 = (j0 < end) ? __ldg(&as_in[s0]) : 0.f;
        float a1 = (j1 < end) ? __ldg(&as_in[s1]) : 0.f;
        float w_self = __expf(leaky(__ldg(&as_in[node]) + ad_n));
        uint2 vsr = hp_row16(hp_in, node, lane16);
        float4 v = agg_body(gmask, pairs, hp_in, as_in, start, end, ad_n, w_self,
                            vsr, s0, s1, a0, a1, lane16);
        v = bias_relu(v, bias, lane16);
        float* o = out + (size_t)node * 64;
        ((float2*)o)[lane16]        = make_float2(v.x, v.z);   // ch 2l, 2l+1
        ((float2*)(o + 32))[lane16] = make_float2(v.y, v.w);   // ch 2l+32, 2l+33
    }
}

// ---------------- host launcher (fork-join: CSR chain || layer-0 GEMM) ----------
extern "C" void kernel_launch(void* const* d_in, const int* in_sizes, int n_in,
                              void* d_out, int out_size) {
    const float* x  = (const float*)d_in[0];
    const int*   ei = (const int*)  d_in[1];
    const float* W0 = (const float*)d_in[4];
    const float* av_s0 = (const float*)d_in[5];
    const float* av_d0 = (const float*)d_in[6];
    const float* b0  = (const float*)d_in[7];
    const float* W1 = (const float*)d_in[8];
    const float* av_s1 = (const float*)d_in[9];
    const float* av_d1 = (const float*)d_in[10];
    const float* b1  = (const float*)d_in[11];
    const float* W2 = (const float*)d_in[12];
    const float* av_s2 = (const float*)d_in[13];
    const float* av_d2 = (const float*)d_in[14];
    const float* b2  = (const float*)d_in[15];

    int n = in_sizes[0] / CIN0;
    int E = in_sizes[1] / 2;
    float* out = (float*)d_out;

    void *degp, *hpA, *hpB, *asA, *adA, *asB, *adB;
    cudaGetSymbolAddress(&degp, g_deg);
    cudaGetSymbolAddress(&hpA, g_hpA);
    cudaGetSymbolAddress(&hpB, g_hpB);
    cudaGetSymbolAddress(&asA, g_asA);
    cudaGetSymbolAddress(&adA, g_adA);
    cudaGetSymbolAddress(&asB, g_asB);
    cudaGetSymbolAddress(&adB, g_adB);

    // lazily created side stream + events (created on first (correctness) call,
    // BEFORE graph capture; no device memory involved)
    static cudaStream_t s2 = nullptr;
    static cudaEvent_t evFork = nullptr, evJoin = nullptr;
    if (s2 == nullptr) {
        cudaStreamCreateWithFlags(&s2, cudaStreamNonBlocking);
        cudaEventCreateWithFlags(&evFork, cudaEventDisableTiming);
        cudaEventCreateWithFlags(&evJoin, cudaEventDisableTiming);
    }

    dim3 gblock(32, 8);
    int ggrid = (n + 31) / 32;
    int tiles = (n + 1023) / 1024;

    cudaMemsetAsync(degp, 0, (size_t)n * sizeof(int), 0);

    // fork: layer-0 GEMM on side stream (independent of CSR)
    cudaEventRecord(evFork, 0);
    cudaStreamWaitEvent(s2, evFork, 0);
    gemm_alpha_kernel<<<ggrid, gblock, 0, s2>>>((const float4*)x, W0, av_s0, av_d0,
                                                (__half2*)hpA, (float*)asA, (float*)adA, n);
    cudaEventRecord(evJoin, s2);

    // main stream: CSR chain
    count_kernel  <<<(E + 2047) / 2048, 256>>>(ei, E);
    scan_sums     <<<tiles, 1024>>>(n);
    scan_write    <<<tiles, 1024>>>(tiles, n);
    scatter_kernel<<<(E + 2047) / 2048, 256>>>(ei, E);

    // join
    cudaStreamWaitEvent(0, evJoin, 0);

    // agg(L0, A) + GEMM(W1) + alpha1 -> buf B
    agg_gemm_kernel<<<ggrid, 256>>>((const __half2*)hpA, (const float*)asA, (const float*)adA,
                                    b0, W1, av_s1, av_d1,
                                    (__half2*)hpB, (float*)asB, (float*)adB, n);
    // agg(L1, B) + GEMM(W2) + alpha2 -> buf A
    agg_gemm_kernel<<<ggrid, 256>>>((const __half2*)hpB, (const float*)asB, (const float*)adB,
                                    b1, W2, av_s2, av_d2,
                                    (__half2*)hpA, (float*)asA, (float*)adA, n);
    // final aggregate -> out (32 nodes/block)
    agg_out_kernel<<<(n + 31) / 32, 256>>>((const __half2*)hpA, (const float*)asA,
                                           (const float*)adA, b2, out, n);
}